// round 5
// baseline (speedup 1.0000x reference)
#include <cuda_runtime.h>
#include <math.h>
#include <stdint.h>

#define SEQ   1024
#define BATCH 4
#define DM    1024
#define NH    16
#define DKH   64
#define DFF   4096
#define ROWS  (BATCH*SEQ)       // 4096
#define QKVS  (3*DM)            // 3072 fused qkv row stride
#define LN_EPS 1e-6f
#define NEGINF -1e9f

// ---------------- scratch (device globals; no allocation) ----------------
__device__ float g_xn [ROWS*DM];
__device__ float g_qkv[(size_t)ROWS*QKVS];            // 48 MB
__device__ float g_sc [(size_t)BATCH*NH*SEQ*SEQ];     // 256 MB
__device__ float g_at [ROWS*DM];
__device__ float g_x1 [ROWS*DM];
__device__ float g_ff [(size_t)ROWS*DFF];             // 64 MB
__device__ float g_wqkv[DM*QKVS];                     // 12 MB
__device__ float g_bqkv[QKVS];
__device__ float g_wo[DM*DM];
__device__ float g_w1[DM*DFF];
__device__ float g_w2[DFF*DM];

// ---------------- helpers ----------------
__device__ __forceinline__ float tf32r(float x) {
    unsigned u;
    asm("cvt.rna.tf32.f32 %0, %1;" : "=r"(u) : "f"(x));
    return __uint_as_float(u);
}
__device__ __forceinline__ unsigned su(const void* p) {
    return (unsigned)__cvta_generic_to_shared(p);
}
#define CPA16(dst, src) asm volatile("cp.async.cg.shared.global [%0], [%1], 16;" :: "r"(dst), "l"(src))
#define CPCOMMIT()      asm volatile("cp.async.commit_group;")
#define CPWAIT1()       asm volatile("cp.async.wait_group 1;")
#define CPWAIT0()       asm volatile("cp.async.wait_group 0;")

__device__ __forceinline__ void mma8(float* c, const unsigned* a, const unsigned* b) {
    asm volatile(
        "mma.sync.aligned.m16n8k8.row.col.f32.tf32.tf32.f32 "
        "{%0,%1,%2,%3}, {%4,%5,%6,%7}, {%8,%9}, {%0,%1,%2,%3};"
        : "+f"(c[0]), "+f"(c[1]), "+f"(c[2]), "+f"(c[3])
        : "r"(a[0]), "r"(a[1]), "r"(a[2]), "r"(a[3]), "r"(b[0]), "r"(b[1]));
}

// ---------------- tf32 rounding (optionally into strided/offset layout) ---
__global__ void round_cat_kernel(const float4* __restrict__ in, float4* __restrict__ out,
                                 int n4, int rowLen4, int stride4, int off4) {
    for (int i = blockIdx.x * blockDim.x + threadIdx.x; i < n4; i += gridDim.x * blockDim.x) {
        float4 v = in[i];
        v.x = tf32r(v.x); v.y = tf32r(v.y); v.z = tf32r(v.z); v.w = tf32r(v.w);
        int r = i / rowLen4, c = i - r * rowLen4;
        out[(size_t)r * stride4 + off4 + c] = v;
    }
}

__global__ void bias_cat_kernel(const float* __restrict__ b0, const float* __restrict__ b1,
                                const float* __restrict__ b2, float* __restrict__ out) {
    int i = blockIdx.x * blockDim.x + threadIdx.x;
    if (i < DM) out[i] = b0[i];
    else if (i < 2*DM) out[i] = b1[i - DM];
    else if (i < 3*DM) out[i] = b2[i - 2*DM];
}

// ---------------- block reductions (256 threads) ----------------
__device__ __forceinline__ float block_sum256(float v, float* red) {
    #pragma unroll
    for (int o = 16; o > 0; o >>= 1) v += __shfl_xor_sync(0xffffffffu, v, o);
    if ((threadIdx.x & 31) == 0) red[threadIdx.x >> 5] = v;
    __syncthreads();
    float t = 0.f;
    #pragma unroll
    for (int i = 0; i < 8; i++) t += red[i];
    __syncthreads();
    return t;
}
__device__ __forceinline__ float block_max256(float v, float* red) {
    #pragma unroll
    for (int o = 16; o > 0; o >>= 1) v = fmaxf(v, __shfl_xor_sync(0xffffffffu, v, o));
    if ((threadIdx.x & 31) == 0) red[threadIdx.x >> 5] = v;
    __syncthreads();
    float t = -INFINITY;
    #pragma unroll
    for (int i = 0; i < 8; i++) t = fmaxf(t, red[i]);
    __syncthreads();
    return t;
}

// ---------------- layernorm (tf32-rounded output) ----------------
__global__ void ln_kernel(const float* __restrict__ x, float* __restrict__ y,
                          const float* __restrict__ alpha, const float* __restrict__ beta) {
    __shared__ float red[8];
    const int row = blockIdx.x;
    const float* xr = x + (size_t)row * DM;
    float*       yr = y + (size_t)row * DM;

    float v[4];
    float s = 0.f;
    #pragma unroll
    for (int i = 0; i < 4; i++) { v[i] = xr[threadIdx.x + i*256]; s += v[i]; }
    const float mean = block_sum256(s, red) * (1.f / DM);

    float d2 = 0.f;
    #pragma unroll
    for (int i = 0; i < 4; i++) { float d = v[i] - mean; d2 += d * d; }
    const float var = block_sum256(d2, red) * (1.f / (DM - 1));
    const float inv = alpha[0] / (sqrtf(var) + LN_EPS);
    const float b0  = beta[0];
    #pragma unroll
    for (int i = 0; i < 4; i++)
        yr[threadIdx.x + i*256] = tf32r((v[i] - mean) * inv + b0);
}

// ---------------- softmax (tf32-rounded output) ----------------
__global__ void softmax_kernel(float* __restrict__ S) {
    __shared__ float red[8];
    float* p = S + (size_t)blockIdx.x * SEQ;
    float v[4];
    float m = -INFINITY;
    #pragma unroll
    for (int i = 0; i < 4; i++) { v[i] = p[threadIdx.x + i*256]; m = fmaxf(m, v[i]); }
    m = block_max256(m, red);
    float s = 0.f;
    #pragma unroll
    for (int i = 0; i < 4; i++) { v[i] = expf(v[i] - m); s += v[i]; }
    s = block_sum256(s, red);
    const float inv = 1.f / s;
    #pragma unroll
    for (int i = 0; i < 4; i++) p[threadIdx.x + i*256] = tf32r(v[i] * inv);
}

// =====================================================================
// tf32 tensor-core GEMM: C = A[M,K] @ B[K,N] (+bias, relu, res, round)
// 128x128 tile, BK=16, 128 threads (4 warps 2x2, warp-tile 64x64)
// =====================================================================
template<bool RELU, bool RES, bool ROUND>
__global__ __launch_bounds__(128, 2)
void gemm_tf32(const float* __restrict__ A, const float* __restrict__ B,
               const float* __restrict__ bias, const float* __restrict__ res,
               float* __restrict__ C, int M, int N, int K) {
    __shared__ float As[2][128][20];    // [m][k]
    __shared__ float Bs[2][16][136];    // [k][n]

    const int tid  = threadIdx.x;
    const int wid  = tid >> 5, lane = tid & 31;
    const int wm   = wid >> 1, wn = wid & 1;
    const int g    = lane >> 2, tig = lane & 3;
    const int bm   = blockIdx.y * 128, bn = blockIdx.x * 128;

    const int a_row = tid >> 2;           // 0..31 (+32,+64,+96)
    const int a_kc  = (tid & 3) << 2;
    const int b_row = tid >> 5;           // 0..3 (+4,+8,+12)
    const int b_nc  = (tid & 31) << 2;

    const float* Ag = A + (size_t)bm * K;
    const float* Bg = B + bn;

    float acc[4][8][4] = {};
    const int NIT = K >> 4;

    // prologue: stage 0
    #pragma unroll
    for (int j = 0; j < 4; j++) {
        CPA16(su(&As[0][a_row + 32*j][a_kc]), Ag + (size_t)(a_row + 32*j) * K + a_kc);
        CPA16(su(&Bs[0][b_row + 4*j][b_nc]),  Bg + (size_t)(b_row + 4*j) * N + b_nc);
    }
    CPCOMMIT();

    for (int it = 0; it < NIT; it++) {
        const int cur = it & 1;
        if (it + 1 < NIT) {
            const int nxt = cur ^ 1;
            const int k0 = (it + 1) << 4;
            #pragma unroll
            for (int j = 0; j < 4; j++) {
                CPA16(su(&As[nxt][a_row + 32*j][a_kc]), Ag + (size_t)(a_row + 32*j) * K + k0 + a_kc);
                CPA16(su(&Bs[nxt][b_row + 4*j][b_nc]),  Bg + (size_t)(k0 + b_row + 4*j) * N + b_nc);
            }
            CPCOMMIT();
            CPWAIT1();
        } else {
            CPWAIT0();
        }
        __syncthreads();

        #pragma unroll
        for (int kt = 0; kt < 2; kt++) {
            const int kb = kt << 3;
            unsigned a[4][4], b[8][2];
            #pragma unroll
            for (int mt = 0; mt < 4; mt++) {
                const int rm = wm*64 + mt*16 + g;
                a[mt][0] = __float_as_uint(As[cur][rm  ][kb+tig]);
                a[mt][1] = __float_as_uint(As[cur][rm+8][kb+tig]);
                a[mt][2] = __float_as_uint(As[cur][rm  ][kb+tig+4]);
                a[mt][3] = __float_as_uint(As[cur][rm+8][kb+tig+4]);
            }
            #pragma unroll
            for (int nt = 0; nt < 8; nt++) {
                const int cn = wn*64 + nt*8 + g;
                b[nt][0] = __float_as_uint(Bs[cur][kb+tig  ][cn]);
                b[nt][1] = __float_as_uint(Bs[cur][kb+tig+4][cn]);
            }
            #pragma unroll
            for (int mt = 0; mt < 4; mt++)
                #pragma unroll
                for (int nt = 0; nt < 8; nt++)
                    mma8(acc[mt][nt], a[mt], b[nt]);
        }
        __syncthreads();
    }

    // epilogue
    #pragma unroll
    for (int mt = 0; mt < 4; mt++) {
        const int r0 = bm + wm*64 + mt*16 + g;
        #pragma unroll
        for (int nt = 0; nt < 8; nt++) {
            const int c0 = bn + wn*64 + nt*8 + 2*tig;
            const float2 bi = *(const float2*)&bias[c0];
            float v0 = acc[mt][nt][0] + bi.x;
            float v1 = acc[mt][nt][1] + bi.y;
            float v2 = acc[mt][nt][2] + bi.x;
            float v3 = acc[mt][nt][3] + bi.y;
            if (RELU) { v0 = fmaxf(v0,0.f); v1 = fmaxf(v1,0.f); v2 = fmaxf(v2,0.f); v3 = fmaxf(v3,0.f); }
            if (RES) {
                const float2 ra = *(const float2*)&res[(size_t)r0*N + c0];
                const float2 rb = *(const float2*)&res[(size_t)(r0+8)*N + c0];
                v0 += ra.x; v1 += ra.y; v2 += rb.x; v3 += rb.y;
            }
            if (ROUND) { v0 = tf32r(v0); v1 = tf32r(v1); v2 = tf32r(v2); v3 = tf32r(v3); }
            *(float2*)&C[(size_t)r0*N + c0]     = make_float2(v0, v1);
            *(float2*)&C[(size_t)(r0+8)*N + c0] = make_float2(v2, v3);
        }
    }
}

// =====================================================================
// scores: S[bh,q,k] = (Q_bh @ K_bh^T)/8, masked.  128x128 tile, Kdim=64
// Q/K read from fused qkv buffer (row stride QKVS)
// =====================================================================
__global__ __launch_bounds__(256, 2)
void scores_tf32(const float* __restrict__ QKV, const int* __restrict__ mask,
                 float* __restrict__ S) {
    __shared__ float As[2][128][20];
    __shared__ float Ks[2][128][20];

    const int tid = threadIdx.x;
    const int wid = tid >> 5, lane = tid & 31;
    const int wm  = wid >> 2, wn = wid & 3;
    const int g   = lane >> 2, tig = lane & 3;

    const int bh = blockIdx.z, b = bh >> 4, h = bh & 15;
    const int q0 = blockIdx.y * 128, k0 = blockIdx.x * 128;

    const int a_row = tid >> 2;
    const int a_kc  = (tid & 3) << 2;

    const float* Qg = QKV + ((size_t)(b*SEQ + q0)) * QKVS + h*DKH;
    const float* Kg = QKV + ((size_t)(b*SEQ + k0)) * QKVS + DM + h*DKH;

    float acc[4][4][4] = {};

    {
        CPA16(su(&As[0][a_row][a_kc]),    Qg + (size_t)a_row * QKVS + a_kc);
        CPA16(su(&As[0][a_row+64][a_kc]), Qg + (size_t)(a_row+64) * QKVS + a_kc);
        CPA16(su(&Ks[0][a_row][a_kc]),    Kg + (size_t)a_row * QKVS + a_kc);
        CPA16(su(&Ks[0][a_row+64][a_kc]), Kg + (size_t)(a_row+64) * QKVS + a_kc);
        CPCOMMIT();
    }

    for (int it = 0; it < 4; it++) {
        const int cur = it & 1;
        if (it + 1 < 4) {
            const int nxt = cur ^ 1;
            const int kd = (it + 1) << 4;
            CPA16(su(&As[nxt][a_row][a_kc]),    Qg + (size_t)a_row * QKVS + kd + a_kc);
            CPA16(su(&As[nxt][a_row+64][a_kc]), Qg + (size_t)(a_row+64) * QKVS + kd + a_kc);
            CPA16(su(&Ks[nxt][a_row][a_kc]),    Kg + (size_t)a_row * QKVS + kd + a_kc);
            CPA16(su(&Ks[nxt][a_row+64][a_kc]), Kg + (size_t)(a_row+64) * QKVS + kd + a_kc);
            CPCOMMIT();
            CPWAIT1();
        } else {
            CPWAIT0();
        }
        __syncthreads();

        #pragma unroll
        for (int kt = 0; kt < 2; kt++) {
            const int kb = kt << 3;
            unsigned a[4][4], bfr[4][2];
            #pragma unroll
            for (int mt = 0; mt < 4; mt++) {
                const int rm = wm*64 + mt*16 + g;
                a[mt][0] = __float_as_uint(As[cur][rm  ][kb+tig]);
                a[mt][1] = __float_as_uint(As[cur][rm+8][kb+tig]);
                a[mt][2] = __float_as_uint(As[cur][rm  ][kb+tig+4]);
                a[mt][3] = __float_as_uint(As[cur][rm+8][kb+tig+4]);
            }
            #pragma unroll
            for (int nt = 0; nt < 4; nt++) {
                const int cn = wn*32 + nt*8 + g;
                bfr[nt][0] = __float_as_uint(Ks[cur][cn][kb+tig]);
                bfr[nt][1] = __float_as_uint(Ks[cur][cn][kb+tig+4]);
            }
            #pragma unroll
            for (int mt = 0; mt < 4; mt++)
                #pragma unroll
                for (int nt = 0; nt < 4; nt++)
                    mma8(acc[mt][nt], a[mt], bfr[nt]);
        }
        __syncthreads();
    }

    float* Sp = S + (size_t)bh * SEQ * SEQ;
    #pragma unroll
    for (int mt = 0; mt < 4; mt++) {
        const int r0 = q0 + wm*64 + mt*16 + g;
        #pragma unroll
        for (int nt = 0; nt < 4; nt++) {
            const int c0 = k0 + wn*32 + nt*8 + 2*tig;
            const int2 mk = *(const int2*)&mask[b*SEQ + c0];
            float v0 = acc[mt][nt][0] * 0.125f;
            float v1 = acc[mt][nt][1] * 0.125f;
            float v2 = acc[mt][nt][2] * 0.125f;
            float v3 = acc[mt][nt][3] * 0.125f;
            if (mk.x == 0) { v0 = NEGINF; v2 = NEGINF; }
            if (mk.y == 0) { v1 = NEGINF; v3 = NEGINF; }
            *(float2*)&Sp[(size_t)r0*SEQ + c0]     = make_float2(v0, v1);
            *(float2*)&Sp[(size_t)(r0+8)*SEQ + c0] = make_float2(v2, v3);
        }
    }
}

// =====================================================================
// attnv: O[b, m, h*64+d] = sum_k P[bh,m,k] * V_qkv[b,k][2048 + h*64+d]
// =====================================================================
__global__ __launch_bounds__(256, 2)
void attnv_tf32(const float* __restrict__ P, const float* __restrict__ QKV,
                float* __restrict__ O) {
    __shared__ float As[2][128][20];
    __shared__ float Bs[2][16][72];

    const int tid = threadIdx.x;
    const int wid = tid >> 5, lane = tid & 31;
    const int wm  = wid >> 1, wn = wid & 1;
    const int g   = lane >> 2, tig = lane & 3;

    const int bh = blockIdx.y, b = bh >> 4, h = bh & 15;
    const int m0 = blockIdx.x * 128;

    const int a_row = tid >> 2;
    const int a_kc  = (tid & 3) << 2;
    const int b_row = tid >> 4;
    const int b_nc  = (tid & 15) << 2;

    const float* Pg = P + ((size_t)bh * SEQ + m0) * SEQ;
    const float* Vg = QKV + (size_t)(b*SEQ) * QKVS + 2*DM + h*DKH;

    float acc[2][4][4] = {};

    {
        CPA16(su(&As[0][a_row][a_kc]),    Pg + (size_t)a_row * SEQ + a_kc);
        CPA16(su(&As[0][a_row+64][a_kc]), Pg + (size_t)(a_row+64) * SEQ + a_kc);
        CPA16(su(&Bs[0][b_row][b_nc]),    Vg + (size_t)b_row * QKVS + b_nc);
        CPCOMMIT();
    }

    for (int it = 0; it < SEQ/16; it++) {
        const int cur = it & 1;
        if (it + 1 < SEQ/16) {
            const int nxt = cur ^ 1;
            const int k0 = (it + 1) << 4;
            CPA16(su(&As[nxt][a_row][a_kc]),    Pg + (size_t)a_row * SEQ + k0 + a_kc);
            CPA16(su(&As[nxt][a_row+64][a_kc]), Pg + (size_t)(a_row+64) * SEQ + k0 + a_kc);
            CPA16(su(&Bs[nxt][b_row][b_nc]),    Vg + (size_t)(k0 + b_row) * QKVS + b_nc);
            CPCOMMIT();
            CPWAIT1();
        } else {
            CPWAIT0();
        }
        __syncthreads();

        #pragma unroll
        for (int kt = 0; kt < 2; kt++) {
            const int kb = kt << 3;
            unsigned a[2][4], bfr[4][2];
            #pragma unroll
            for (int mt = 0; mt < 2; mt++) {
                const int rm = wm*32 + mt*16 + g;
                a[mt][0] = __float_as_uint(As[cur][rm  ][kb+tig]);
                a[mt][1] = __float_as_uint(As[cur][rm+8][kb+tig]);
                a[mt][2] = __float_as_uint(As[cur][rm  ][kb+tig+4]);
                a[mt][3] = __float_as_uint(As[cur][rm+8][kb+tig+4]);
            }
            #pragma unroll
            for (int nt = 0; nt < 4; nt++) {
                const int cn = wn*32 + nt*8 + g;
                bfr[nt][0] = __float_as_uint(Bs[cur][kb+tig  ][cn]);
                bfr[nt][1] = __float_as_uint(Bs[cur][kb+tig+4][cn]);
            }
            #pragma unroll
            for (int mt = 0; mt < 2; mt++)
                #pragma unroll
                for (int nt = 0; nt < 4; nt++)
                    mma8(acc[mt][nt], a[mt], bfr[nt]);
        }
        __syncthreads();
    }

    #pragma unroll
    for (int mt = 0; mt < 2; mt++) {
        const int r0 = m0 + wm*32 + mt*16 + g;
        #pragma unroll
        for (int nt = 0; nt < 4; nt++) {
            const int c0 = wn*32 + nt*8 + 2*tig;
            float v0 = tf32r(acc[mt][nt][0]);
            float v1 = tf32r(acc[mt][nt][1]);
            float v2 = tf32r(acc[mt][nt][2]);
            float v3 = tf32r(acc[mt][nt][3]);
            *(float2*)&O[(size_t)(b*SEQ + r0)*DM + h*DKH + c0]     = make_float2(v0, v1);
            *(float2*)&O[(size_t)(b*SEQ + r0 + 8)*DM + h*DKH + c0] = make_float2(v2, v3);
        }
    }
}

// ---------------- launch ----------------
extern "C" void kernel_launch(void* const* d_in, const int* in_sizes, int n_in,
                              void* d_out, int out_size) {
    const float* x   = (const float*)d_in[0];
    const int*   mask= (const int*)  d_in[1];
    const float* Wq  = (const float*)d_in[2];
    const float* bq  = (const float*)d_in[3];
    const float* Wk  = (const float*)d_in[4];
    const float* bk  = (const float*)d_in[5];
    const float* Wv  = (const float*)d_in[6];
    const float* bv  = (const float*)d_in[7];
    const float* Wo  = (const float*)d_in[8];
    const float* bo  = (const float*)d_in[9];
    const float* W1  = (const float*)d_in[10];
    const float* b1  = (const float*)d_in[11];
    const float* W2  = (const float*)d_in[12];
    const float* b2  = (const float*)d_in[13];
    const float* a1  = (const float*)d_in[14];
    const float* be1 = (const float*)d_in[15];
    const float* a2  = (const float*)d_in[16];
    const float* be2 = (const float*)d_in[17];
    float* out = (float*)d_out;

    float *xn, *qkv, *sc, *at, *x1, *ff, *wqkv, *bqkv, *wo, *w1, *w2;
    cudaGetSymbolAddress((void**)&xn,   g_xn);
    cudaGetSymbolAddress((void**)&qkv,  g_qkv);
    cudaGetSymbolAddress((void**)&sc,   g_sc);
    cudaGetSymbolAddress((void**)&at,   g_at);
    cudaGetSymbolAddress((void**)&x1,   g_x1);
    cudaGetSymbolAddress((void**)&ff,   g_ff);
    cudaGetSymbolAddress((void**)&wqkv, g_wqkv);
    cudaGetSymbolAddress((void**)&bqkv, g_bqkv);
    cudaGetSymbolAddress((void**)&wo,   g_wo);
    cudaGetSymbolAddress((void**)&w1,   g_w1);
    cudaGetSymbolAddress((void**)&w2,   g_w2);

    const int R4 = DM/4;   // 256 float4 per weight row

    // 0) round weights to tf32 (QKV concatenated into one [DM, 3072] buffer)
    round_cat_kernel<<<512, 256>>>((const float4*)Wq, (float4*)wqkv, DM*DM/4, R4, 3*R4, 0);
    round_cat_kernel<<<512, 256>>>((const float4*)Wk, (float4*)wqkv, DM*DM/4, R4, 3*R4, R4);
    round_cat_kernel<<<512, 256>>>((const float4*)Wv, (float4*)wqkv, DM*DM/4, R4, 3*R4, 2*R4);
    round_cat_kernel<<<512, 256>>>((const float4*)Wo, (float4*)wo,   DM*DM/4, R4, R4, 0);
    round_cat_kernel<<<1024, 256>>>((const float4*)W1, (float4*)w1, DM*DFF/4, DFF/4, DFF/4, 0);
    round_cat_kernel<<<1024, 256>>>((const float4*)W2, (float4*)w2, DFF*DM/4, R4, R4, 0);
    bias_cat_kernel<<<QKVS/256, 256>>>(bq, bk, bv, bqkv);

    // 1) LN1
    ln_kernel<<<ROWS, 256>>>(x, xn, a1, be1);
    // 2) fused QKV projection: [4096,1024] @ [1024,3072]
    gemm_tf32<false,false,true><<<dim3(QKVS/128, ROWS/128), 128>>>(xn, wqkv, bqkv, nullptr, qkv, ROWS, QKVS, DM);
    // 3) scores
    scores_tf32<<<dim3(SEQ/128, SEQ/128, BATCH*NH), 256>>>(qkv, mask, sc);
    // 4) softmax
    softmax_kernel<<<BATCH*NH*SEQ, 256>>>(sc);
    // 5) attn @ V
    attnv_tf32<<<dim3(SEQ/128, BATCH*NH), 256>>>(sc, qkv, at);
    // 6) output projection + residual(x)
    gemm_tf32<false,true,false><<<dim3(DM/128, ROWS/128), 128>>>(at, wo, bo, x, x1, ROWS, DM, DM);
    // 7) LN2
    ln_kernel<<<ROWS, 256>>>(x1, xn, a2, be2);
    // 8) FFN up + relu
    gemm_tf32<true,false,true><<<dim3(DFF/128, ROWS/128), 128>>>(xn, w1, b1, nullptr, ff, ROWS, DFF, DM);
    // 9) FFN down + residual(x1) -> out
    gemm_tf32<false,true,false><<<dim3(DM/128, ROWS/128), 128>>>(ff, w2, b2, x1, out, ROWS, DM, DFF);
}

// round 6
// speedup vs baseline: 1.0885x; 1.0885x over previous
#include <cuda_runtime.h>
#include <math.h>
#include <stdint.h>

#define SEQ   1024
#define BATCH 4
#define DM    1024
#define NH    16
#define DKH   64
#define DFF   4096
#define ROWS  (BATCH*SEQ)       // 4096
#define QKVS  (3*DM)            // 3072 fused qkv row stride
#define LN_EPS 1e-6f
#define NEGINF -1e9f

// ---------------- scratch (device globals; no allocation) ----------------
__device__ float g_xn [ROWS*DM];
__device__ float g_qkv[(size_t)ROWS*QKVS];            // 48 MB
__device__ float g_at [ROWS*DM];
__device__ float g_x1 [ROWS*DM];
__device__ float g_ff [(size_t)ROWS*DFF];             // 64 MB
__device__ float g_wqkv[DM*QKVS];                     // 12 MB
__device__ float g_bqkv[QKVS];
__device__ float g_wo[DM*DM];
__device__ float g_w1[DM*DFF];
__device__ float g_w2[DFF*DM];

// ---------------- helpers ----------------
__device__ __forceinline__ float tf32r(float x) {
    unsigned u;
    asm("cvt.rna.tf32.f32 %0, %1;" : "=r"(u) : "f"(x));
    return __uint_as_float(u);
}
__device__ __forceinline__ unsigned su(const void* p) {
    return (unsigned)__cvta_generic_to_shared(p);
}
#define CPA16(dst, src) asm volatile("cp.async.cg.shared.global [%0], [%1], 16;" :: "r"(dst), "l"(src))
#define CPCOMMIT()      asm volatile("cp.async.commit_group;")
#define CPWAIT1()       asm volatile("cp.async.wait_group 1;")
#define CPWAIT0()       asm volatile("cp.async.wait_group 0;")

__device__ __forceinline__ void mma8(float* c, const unsigned* a, const unsigned* b) {
    asm volatile(
        "mma.sync.aligned.m16n8k8.row.col.f32.tf32.tf32.f32 "
        "{%0,%1,%2,%3}, {%4,%5,%6,%7}, {%8,%9}, {%0,%1,%2,%3};"
        : "+f"(c[0]), "+f"(c[1]), "+f"(c[2]), "+f"(c[3])
        : "r"(a[0]), "r"(a[1]), "r"(a[2]), "r"(a[3]), "r"(b[0]), "r"(b[1]));
}

// ---------------- tf32 rounding (strided/offset layouts) ----------------
__global__ void round_cat_kernel(const float4* __restrict__ in, float4* __restrict__ out,
                                 int n4, int rowLen4, int stride4, int off4) {
    for (int i = blockIdx.x * blockDim.x + threadIdx.x; i < n4; i += gridDim.x * blockDim.x) {
        float4 v = in[i];
        v.x = tf32r(v.x); v.y = tf32r(v.y); v.z = tf32r(v.z); v.w = tf32r(v.w);
        int r = i / rowLen4, c = i - r * rowLen4;
        out[(size_t)r * stride4 + off4 + c] = v;
    }
}

__global__ void bias_cat_kernel(const float* __restrict__ b0, const float* __restrict__ b1,
                                const float* __restrict__ b2, float* __restrict__ out) {
    int i = blockIdx.x * blockDim.x + threadIdx.x;
    if (i < DM) out[i] = b0[i];
    else if (i < 2*DM) out[i] = b1[i - DM];
    else if (i < 3*DM) out[i] = b2[i - 2*DM];
}

// ---------------- block reductions (256 threads) ----------------
__device__ __forceinline__ float block_sum256(float v, float* red) {
    #pragma unroll
    for (int o = 16; o > 0; o >>= 1) v += __shfl_xor_sync(0xffffffffu, v, o);
    if ((threadIdx.x & 31) == 0) red[threadIdx.x >> 5] = v;
    __syncthreads();
    float t = 0.f;
    #pragma unroll
    for (int i = 0; i < 8; i++) t += red[i];
    __syncthreads();
    return t;
}

// ---------------- layernorm (tf32-rounded output) ----------------
__global__ void ln_kernel(const float* __restrict__ x, float* __restrict__ y,
                          const float* __restrict__ alpha, const float* __restrict__ beta) {
    __shared__ float red[8];
    const int row = blockIdx.x;
    const float* xr = x + (size_t)row * DM;
    float*       yr = y + (size_t)row * DM;

    float v[4];
    float s = 0.f;
    #pragma unroll
    for (int i = 0; i < 4; i++) { v[i] = xr[threadIdx.x + i*256]; s += v[i]; }
    const float mean = block_sum256(s, red) * (1.f / DM);

    float d2 = 0.f;
    #pragma unroll
    for (int i = 0; i < 4; i++) { float d = v[i] - mean; d2 += d * d; }
    const float var = block_sum256(d2, red) * (1.f / (DM - 1));
    const float inv = alpha[0] / (sqrtf(var) + LN_EPS);
    const float b0  = beta[0];
    #pragma unroll
    for (int i = 0; i < 4; i++)
        yr[threadIdx.x + i*256] = tf32r((v[i] - mean) * inv + b0);
}

// =====================================================================
// tf32 tensor-core GEMM: C = A[M,K] @ B[K,N] (+bias, relu, res, round)
// 128x128 tile, BK=16, 128 threads (4 warps 2x2, warp-tile 64x64)
// =====================================================================
template<bool RELU, bool RES, bool ROUND>
__global__ __launch_bounds__(128, 2)
void gemm_tf32(const float* __restrict__ A, const float* __restrict__ B,
               const float* __restrict__ bias, const float* __restrict__ res,
               float* __restrict__ C, int M, int N, int K) {
    __shared__ float As[2][128][20];    // [m][k]
    __shared__ float Bs[2][16][136];    // [k][n]

    const int tid  = threadIdx.x;
    const int wid  = tid >> 5, lane = tid & 31;
    const int wm   = wid >> 1, wn = wid & 1;
    const int g    = lane >> 2, tig = lane & 3;
    const int bm   = blockIdx.y * 128, bn = blockIdx.x * 128;

    const int a_row = tid >> 2;
    const int a_kc  = (tid & 3) << 2;
    const int b_row = tid >> 5;
    const int b_nc  = (tid & 31) << 2;

    const float* Ag = A + (size_t)bm * K;
    const float* Bg = B + bn;

    float acc[4][8][4] = {};
    const int NIT = K >> 4;

    #pragma unroll
    for (int j = 0; j < 4; j++) {
        CPA16(su(&As[0][a_row + 32*j][a_kc]), Ag + (size_t)(a_row + 32*j) * K + a_kc);
        CPA16(su(&Bs[0][b_row + 4*j][b_nc]),  Bg + (size_t)(b_row + 4*j) * N + b_nc);
    }
    CPCOMMIT();

    for (int it = 0; it < NIT; it++) {
        const int cur = it & 1;
        if (it + 1 < NIT) {
            const int nxt = cur ^ 1;
            const int k0 = (it + 1) << 4;
            #pragma unroll
            for (int j = 0; j < 4; j++) {
                CPA16(su(&As[nxt][a_row + 32*j][a_kc]), Ag + (size_t)(a_row + 32*j) * K + k0 + a_kc);
                CPA16(su(&Bs[nxt][b_row + 4*j][b_nc]),  Bg + (size_t)(k0 + b_row + 4*j) * N + b_nc);
            }
            CPCOMMIT();
            CPWAIT1();
        } else {
            CPWAIT0();
        }
        __syncthreads();

        #pragma unroll
        for (int kt = 0; kt < 2; kt++) {
            const int kb = kt << 3;
            unsigned a[4][4], b[8][2];
            #pragma unroll
            for (int mt = 0; mt < 4; mt++) {
                const int rm = wm*64 + mt*16 + g;
                a[mt][0] = __float_as_uint(As[cur][rm  ][kb+tig]);
                a[mt][1] = __float_as_uint(As[cur][rm+8][kb+tig]);
                a[mt][2] = __float_as_uint(As[cur][rm  ][kb+tig+4]);
                a[mt][3] = __float_as_uint(As[cur][rm+8][kb+tig+4]);
            }
            #pragma unroll
            for (int nt = 0; nt < 8; nt++) {
                const int cn = wn*64 + nt*8 + g;
                b[nt][0] = __float_as_uint(Bs[cur][kb+tig  ][cn]);
                b[nt][1] = __float_as_uint(Bs[cur][kb+tig+4][cn]);
            }
            #pragma unroll
            for (int mt = 0; mt < 4; mt++)
                #pragma unroll
                for (int nt = 0; nt < 8; nt++)
                    mma8(acc[mt][nt], a[mt], b[nt]);
        }
        __syncthreads();
    }

    #pragma unroll
    for (int mt = 0; mt < 4; mt++) {
        const int r0 = bm + wm*64 + mt*16 + g;
        #pragma unroll
        for (int nt = 0; nt < 8; nt++) {
            const int c0 = bn + wn*64 + nt*8 + 2*tig;
            const float2 bi = *(const float2*)&bias[c0];
            float v0 = acc[mt][nt][0] + bi.x;
            float v1 = acc[mt][nt][1] + bi.y;
            float v2 = acc[mt][nt][2] + bi.x;
            float v3 = acc[mt][nt][3] + bi.y;
            if (RELU) { v0 = fmaxf(v0,0.f); v1 = fmaxf(v1,0.f); v2 = fmaxf(v2,0.f); v3 = fmaxf(v3,0.f); }
            if (RES) {
                const float2 ra = *(const float2*)&res[(size_t)r0*N + c0];
                const float2 rb = *(const float2*)&res[(size_t)(r0+8)*N + c0];
                v0 += ra.x; v1 += ra.y; v2 += rb.x; v3 += rb.y;
            }
            if (ROUND) { v0 = tf32r(v0); v1 = tf32r(v1); v2 = tf32r(v2); v3 = tf32r(v3); }
            *(float2*)&C[(size_t)r0*N + c0]     = make_float2(v0, v1);
            *(float2*)&C[(size_t)(r0+8)*N + c0] = make_float2(v2, v3);
        }
    }
}

// =====================================================================
// flash attention: per block, 128 q-rows of one (b,h). 256 thr, 8 warps.
// warp w owns rows [16w, 16w+16) in BOTH the S-mma and the PV-mma.
// smem: Qs[128][68] Ks[2][128][68] Vs[128][72] Ps[128][132]  = 204 KB
// =====================================================================
#define QSTR 68
#define VSTR 72
#define PSTR 132
#define FA_SMEM ((8704 + 17408 + 9216 + 16896) * 4)

__global__ __launch_bounds__(256, 1)
void flash_kernel(const float* __restrict__ QKV, const int* __restrict__ mask,
                  float* __restrict__ O) {
    extern __shared__ float smf[];
    float* Qs = smf;                    // [128][68]
    float* Ks = smf + 8704;             // [2][128][68]
    float* Vs = smf + 26112;            // [128][72]
    float* Ps = smf + 35328;            // [128][132]

    const int tid = threadIdx.x, wid = tid >> 5, lane = tid & 31;
    const int g = lane >> 2, tig = lane & 3;
    const int bh = blockIdx.y, b = bh >> 4, h = bh & 15;
    const int q0 = blockIdx.x * 128;

    const float* Qg = QKV + (size_t)(b*SEQ + q0) * QKVS + h*DKH;
    const float* Kg = QKV + (size_t)(b*SEQ) * QKVS + DM + h*DKH;
    const float* Vg = QKV + (size_t)(b*SEQ) * QKVS + 2*DM + h*DKH;

    const int lr = tid >> 2;            // 0..63
    const int lc = (tid & 3) * 16;      // 0,16,32,48

    // prologue: Q + K0 + V0 (one group)
    #pragma unroll
    for (int j = 0; j < 2; j++)
        #pragma unroll
        for (int i = 0; i < 4; i++) {
            const int row = lr + 64*j, col = lc + 4*i;
            CPA16(su(&Qs[row*QSTR + col]), Qg + (size_t)row*QKVS + col);
            CPA16(su(&Ks[row*QSTR + col]), Kg + (size_t)row*QKVS + col);
            CPA16(su(&Vs[row*VSTR + col]), Vg + (size_t)row*QKVS + col);
        }
    CPCOMMIT();

    float m0 = -INFINITY, m1 = -INFINITY, l0 = 0.f, l1 = 0.f;
    float acc_o[8][4] = {};
    const int rm = wid*16 + g;

    for (int it = 0; it < 8; it++) {
        const int cur = it & 1;
        const float* Kc = Ks + cur*8704;
        if (it == 0) { CPWAIT0(); } else { CPWAIT1(); }
        __syncthreads();

        // prefetch next K tile
        if (it + 1 < 8) {
            float* Kn = Ks + (cur^1)*8704;
            const float* Kgn = Kg + (size_t)(it+1)*128*QKVS;
            #pragma unroll
            for (int j = 0; j < 2; j++)
                #pragma unroll
                for (int i = 0; i < 4; i++) {
                    const int row = lr + 64*j, col = lc + 4*i;
                    CPA16(su(&Kn[row*QSTR + col]), Kgn + (size_t)row*QKVS + col);
                }
            CPCOMMIT();
        }

        // ---- S = Q K^T (this warp: rows rm, rm+8; all 128 n-cols)
        float s[16][4];
        #pragma unroll
        for (int nt = 0; nt < 16; nt++) { s[nt][0]=0.f; s[nt][1]=0.f; s[nt][2]=0.f; s[nt][3]=0.f; }
        #pragma unroll
        for (int kb = 0; kb < 64; kb += 8) {
            unsigned a[4], bf[16][2];
            a[0] = __float_as_uint(Qs[rm*QSTR + kb + tig]);
            a[1] = __float_as_uint(Qs[(rm+8)*QSTR + kb + tig]);
            a[2] = __float_as_uint(Qs[rm*QSTR + kb + tig + 4]);
            a[3] = __float_as_uint(Qs[(rm+8)*QSTR + kb + tig + 4]);
            #pragma unroll
            for (int nt = 0; nt < 16; nt++) {
                const int cn = nt*8 + g;
                bf[nt][0] = __float_as_uint(Kc[cn*QSTR + kb + tig]);
                bf[nt][1] = __float_as_uint(Kc[cn*QSTR + kb + tig + 4]);
            }
            #pragma unroll
            for (int nt = 0; nt < 16; nt++) mma8(s[nt], a, bf[nt]);
        }

        // ---- scale + mask + online softmax
        const int kbase = b*SEQ + it*128;
        float tm0 = -INFINITY, tm1 = -INFINITY;
        #pragma unroll
        for (int nt = 0; nt < 16; nt++) {
            const int2 mk = *(const int2*)&mask[kbase + nt*8 + 2*tig];
            float v0 = s[nt][0]*0.125f, v1 = s[nt][1]*0.125f;
            float v2 = s[nt][2]*0.125f, v3 = s[nt][3]*0.125f;
            if (mk.x == 0) { v0 = NEGINF; v2 = NEGINF; }
            if (mk.y == 0) { v1 = NEGINF; v3 = NEGINF; }
            s[nt][0]=v0; s[nt][1]=v1; s[nt][2]=v2; s[nt][3]=v3;
            tm0 = fmaxf(tm0, fmaxf(v0, v1));
            tm1 = fmaxf(tm1, fmaxf(v2, v3));
        }
        tm0 = fmaxf(tm0, __shfl_xor_sync(0xffffffffu, tm0, 1));
        tm0 = fmaxf(tm0, __shfl_xor_sync(0xffffffffu, tm0, 2));
        tm1 = fmaxf(tm1, __shfl_xor_sync(0xffffffffu, tm1, 1));
        tm1 = fmaxf(tm1, __shfl_xor_sync(0xffffffffu, tm1, 2));
        const float mn0 = fmaxf(m0, tm0), mn1 = fmaxf(m1, tm1);
        const float sc0 = __expf(m0 - mn0), sc1 = __expf(m1 - mn1);
        m0 = mn0; m1 = mn1;
        l0 *= sc0; l1 *= sc1;
        #pragma unroll
        for (int nt = 0; nt < 8; nt++) {
            acc_o[nt][0] *= sc0; acc_o[nt][1] *= sc0;
            acc_o[nt][2] *= sc1; acc_o[nt][3] *= sc1;
        }
        float rs0 = 0.f, rs1 = 0.f;
        #pragma unroll
        for (int nt = 0; nt < 16; nt++) {
            const float p0 = __expf(s[nt][0] - mn0), p1 = __expf(s[nt][1] - mn0);
            const float p2 = __expf(s[nt][2] - mn1), p3 = __expf(s[nt][3] - mn1);
            rs0 += p0 + p1; rs1 += p2 + p3;
            const int cc = nt*8 + 2*tig;
            *(float2*)&Ps[rm*PSTR + cc]     = make_float2(tf32r(p0), tf32r(p1));
            *(float2*)&Ps[(rm+8)*PSTR + cc] = make_float2(tf32r(p2), tf32r(p3));
        }
        rs0 += __shfl_xor_sync(0xffffffffu, rs0, 1);
        rs0 += __shfl_xor_sync(0xffffffffu, rs0, 2);
        rs1 += __shfl_xor_sync(0xffffffffu, rs1, 1);
        rs1 += __shfl_xor_sync(0xffffffffu, rs1, 2);
        l0 += rs0; l1 += rs1;
        __syncwarp();                    // Ps rows are warp-private; order STS->LDS

        // ---- wait for V visible to all, then O += P @ V
        CPWAIT0();
        __syncthreads();
        #pragma unroll
        for (int kb = 0; kb < 128; kb += 8) {
            unsigned a[4], bf[8][2];
            a[0] = __float_as_uint(Ps[rm*PSTR + kb + tig]);
            a[1] = __float_as_uint(Ps[(rm+8)*PSTR + kb + tig]);
            a[2] = __float_as_uint(Ps[rm*PSTR + kb + tig + 4]);
            a[3] = __float_as_uint(Ps[(rm+8)*PSTR + kb + tig + 4]);
            #pragma unroll
            for (int nt = 0; nt < 8; nt++) {
                const int cn = nt*8 + g;
                bf[nt][0] = __float_as_uint(Vs[(kb+tig)*VSTR + cn]);
                bf[nt][1] = __float_as_uint(Vs[(kb+tig+4)*VSTR + cn]);
            }
            #pragma unroll
            for (int nt = 0; nt < 8; nt++) mma8(acc_o[nt], a, bf[nt]);
        }
        __syncthreads();                 // all warps done reading Vs

        // issue next V tile (latency hidden behind next iter's S phase)
        if (it + 1 < 8) {
            const float* Vgn = Vg + (size_t)(it+1)*128*QKVS;
            #pragma unroll
            for (int j = 0; j < 2; j++)
                #pragma unroll
                for (int i = 0; i < 4; i++) {
                    const int row = lr + 64*j, col = lc + 4*i;
                    CPA16(su(&Vs[row*VSTR + col]), Vgn + (size_t)row*QKVS + col);
                }
            CPCOMMIT();
        }
    }

    // ---- epilogue: O / l, tf32-rounded
    const float inv0 = 1.f / l0, inv1 = 1.f / l1;
    float* Op  = O + (size_t)(b*SEQ + q0 + rm) * DM + h*DKH;
    float* Op8 = Op + (size_t)8 * DM;
    #pragma unroll
    for (int nt = 0; nt < 8; nt++) {
        const int cc = nt*8 + 2*tig;
        *(float2*)&Op[cc]  = make_float2(tf32r(acc_o[nt][0]*inv0), tf32r(acc_o[nt][1]*inv0));
        *(float2*)&Op8[cc] = make_float2(tf32r(acc_o[nt][2]*inv1), tf32r(acc_o[nt][3]*inv1));
    }
}

// ---------------- launch ----------------
extern "C" void kernel_launch(void* const* d_in, const int* in_sizes, int n_in,
                              void* d_out, int out_size) {
    const float* x   = (const float*)d_in[0];
    const int*   mask= (const int*)  d_in[1];
    const float* Wq  = (const float*)d_in[2];
    const float* bq  = (const float*)d_in[3];
    const float* Wk  = (const float*)d_in[4];
    const float* bk  = (const float*)d_in[5];
    const float* Wv  = (const float*)d_in[6];
    const float* bv  = (const float*)d_in[7];
    const float* Wo  = (const float*)d_in[8];
    const float* bo  = (const float*)d_in[9];
    const float* W1  = (const float*)d_in[10];
    const float* b1  = (const float*)d_in[11];
    const float* W2  = (const float*)d_in[12];
    const float* b2  = (const float*)d_in[13];
    const float* a1  = (const float*)d_in[14];
    const float* be1 = (const float*)d_in[15];
    const float* a2  = (const float*)d_in[16];
    const float* be2 = (const float*)d_in[17];
    float* out = (float*)d_out;

    float *xn, *qkv, *at, *x1, *ff, *wqkv, *bqkv, *wo, *w1, *w2;
    cudaGetSymbolAddress((void**)&xn,   g_xn);
    cudaGetSymbolAddress((void**)&qkv,  g_qkv);
    cudaGetSymbolAddress((void**)&at,   g_at);
    cudaGetSymbolAddress((void**)&x1,   g_x1);
    cudaGetSymbolAddress((void**)&ff,   g_ff);
    cudaGetSymbolAddress((void**)&wqkv, g_wqkv);
    cudaGetSymbolAddress((void**)&bqkv, g_bqkv);
    cudaGetSymbolAddress((void**)&wo,   g_wo);
    cudaGetSymbolAddress((void**)&w1,   g_w1);
    cudaGetSymbolAddress((void**)&w2,   g_w2);

    cudaFuncSetAttribute(flash_kernel, cudaFuncAttributeMaxDynamicSharedMemorySize, FA_SMEM);

    const int R4 = DM/4;

    // 0) round weights to tf32 (QKV concatenated into one [DM, 3072] buffer)
    round_cat_kernel<<<512, 256>>>((const float4*)Wq, (float4*)wqkv, DM*DM/4, R4, 3*R4, 0);
    round_cat_kernel<<<512, 256>>>((const float4*)Wk, (float4*)wqkv, DM*DM/4, R4, 3*R4, R4);
    round_cat_kernel<<<512, 256>>>((const float4*)Wv, (float4*)wqkv, DM*DM/4, R4, 3*R4, 2*R4);
    round_cat_kernel<<<512, 256>>>((const float4*)Wo, (float4*)wo,   DM*DM/4, R4, R4, 0);
    round_cat_kernel<<<1024, 256>>>((const float4*)W1, (float4*)w1, DM*DFF/4, DFF/4, DFF/4, 0);
    round_cat_kernel<<<1024, 256>>>((const float4*)W2, (float4*)w2, DFF*DM/4, R4, R4, 0);
    bias_cat_kernel<<<QKVS/256, 256>>>(bq, bk, bv, bqkv);

    // 1) LN1
    ln_kernel<<<ROWS, 256>>>(x, xn, a1, be1);
    // 2) fused QKV projection: [4096,1024] @ [1024,3072]
    gemm_tf32<false,false,true><<<dim3(QKVS/128, ROWS/128), 128>>>(xn, wqkv, bqkv, nullptr, qkv, ROWS, QKVS, DM);
    // 3) fused attention (scores + softmax + attn@V)
    flash_kernel<<<dim3(SEQ/128, BATCH*NH), 256, FA_SMEM>>>(qkv, mask, at);
    // 4) output projection + residual(x)
    gemm_tf32<false,true,false><<<dim3(DM/128, ROWS/128), 128>>>(at, wo, bo, x, x1, ROWS, DM, DM);
    // 5) LN2
    ln_kernel<<<ROWS, 256>>>(x1, xn, a2, be2);
    // 6) FFN up + relu
    gemm_tf32<true,false,true><<<dim3(DFF/128, ROWS/128), 128>>>(xn, w1, b1, nullptr, ff, ROWS, DFF, DM);
    // 7) FFN down + residual(x1) -> out
    gemm_tf32<false,true,false><<<dim3(DM/128, ROWS/128), 128>>>(ff, w2, b2, x1, out, ROWS, DM, DFF);
}